// round 3
// baseline (speedup 1.0000x reference)
#include <cuda_runtime.h>
#include <cuda_bf16.h>

#define B_  4
#define H_  16
#define LQ_ 2048
#define LK_ 2048
#define DM_ 1024
#define DK_ 64
#define DV_ 64

// ---- device scratch (allocation-free rule: __device__ globals) ----
__device__ float g_Q[B_ * H_ * LQ_ * DK_];      // (B,H,LQ,DK)
__device__ float g_K[B_ * H_ * LK_ * DK_];      // (B,H,LK,DK)
__device__ float g_V[B_ * H_ * LK_ * DV_];      // (B,H,LK,DV)
__device__ float g_ctx[B_ * LQ_ * H_ * DV_];    // (B,LQ,H*DV)
__device__ float g_attn_fb[B_ * H_ * LQ_ * LK_]; // fallback attn scratch (1 GiB)

// ============================================================================
// Projection GEMM: Out[b,h,l,e] = sum_d A[b*LQ+l, d] * W[h,d,e]
// Viewed as GEMM M=8192, N=H*64=1024, K=1024. 128x128x16 tile, 256 thr, 8x8.
// ============================================================================
__global__ void __launch_bounds__(256) proj_kernel(const float* __restrict__ A,
                                                   const float* __restrict__ W,
                                                   float* __restrict__ Out)
{
    __shared__ float As[16][132];
    __shared__ float Bs[16][132];
    const int tid = threadIdx.x;
    const int tx = tid & 15;
    const int ty = tid >> 4;
    const int row0 = blockIdx.y * 128;
    const int col0 = blockIdx.x * 128;

    float acc[8][8];
#pragma unroll
    for (int i = 0; i < 8; i++)
#pragma unroll
        for (int j = 0; j < 8; j++) acc[i][j] = 0.f;

    for (int k0 = 0; k0 < DM_; k0 += 16) {
#pragma unroll
        for (int i = 0; i < 2; i++) {
            int idx = tid + i * 256;
            int ar = idx >> 2;
            int ac = (idx & 3) << 2;
            float4 v = *(const float4*)&A[(size_t)(row0 + ar) * DM_ + k0 + ac];
            As[ac + 0][ar] = v.x; As[ac + 1][ar] = v.y;
            As[ac + 2][ar] = v.z; As[ac + 3][ar] = v.w;
        }
#pragma unroll
        for (int i = 0; i < 2; i++) {
            int idx = tid + i * 256;
            int br = idx >> 5;
            int bc = (idx & 31) << 2;
            int n = col0 + bc;
            int h = n >> 6, e = n & 63;
            float4 v = *(const float4*)&W[(size_t)((h << 10) + k0 + br) * 64 + e];
            *(float4*)&Bs[br][bc] = v;
        }
        __syncthreads();
#pragma unroll
        for (int k = 0; k < 16; k++) {
            float4 a0 = *(const float4*)&As[k][ty * 8];
            float4 a1 = *(const float4*)&As[k][ty * 8 + 4];
            float4 b0 = *(const float4*)&Bs[k][tx * 4];
            float4 b1 = *(const float4*)&Bs[k][64 + tx * 4];
            float a[8] = {a0.x, a0.y, a0.z, a0.w, a1.x, a1.y, a1.z, a1.w};
            float b[8] = {b0.x, b0.y, b0.z, b0.w, b1.x, b1.y, b1.z, b1.w};
#pragma unroll
            for (int i = 0; i < 8; i++)
#pragma unroll
                for (int j = 0; j < 8; j++)
                    acc[i][j] = fmaf(a[i], b[j], acc[i][j]);
        }
        __syncthreads();
    }

    const int n0 = col0 + tx * 4;
    const int h0 = n0 >> 6, e0 = n0 & 63;
#pragma unroll
    for (int i = 0; i < 8; i++) {
        int row = row0 + ty * 8 + i;
        int b = row >> 11, l = row & 2047;
        float4 s0 = make_float4(acc[i][0], acc[i][1], acc[i][2], acc[i][3]);
        float4 s1 = make_float4(acc[i][4], acc[i][5], acc[i][6], acc[i][7]);
        *(float4*)&Out[(size_t)(((b << 4) + h0) * 2048 + l) * 64 + e0] = s0;
        *(float4*)&Out[(size_t)(((b << 4) + h0 + 1) * 2048 + l) * 64 + e0] = s1;
    }
}

// ============================================================================
// Scores: S[bh, q, k] = scale * sum_e Q[bh,q,e] * K[bh,k,e]
// Per (b,h): 2048x2048x64. 128x128 tile, K in two 32-chunks. scale fused.
// ============================================================================
__global__ void __launch_bounds__(256) scores_kernel(float* __restrict__ S)
{
    __shared__ float Qs[32][132];
    __shared__ float Ks[32][132];
    const int tid = threadIdx.x;
    const int tx = tid & 15;
    const int ty = tid >> 4;
    const int bh = blockIdx.z;
    const int row0 = blockIdx.y * 128;
    const int col0 = blockIdx.x * 128;
    const float* Q = g_Q + (size_t)bh * LQ_ * DK_;
    const float* Km = g_K + (size_t)bh * LK_ * DK_;

    float acc[8][8];
#pragma unroll
    for (int i = 0; i < 8; i++)
#pragma unroll
        for (int j = 0; j < 8; j++) acc[i][j] = 0.f;

    for (int k0 = 0; k0 < DK_; k0 += 32) {
#pragma unroll
        for (int i = 0; i < 4; i++) {
            int idx = tid + i * 256;
            int r = idx >> 3;
            int c = (idx & 7) << 2;
            float4 v = *(const float4*)&Q[(size_t)(row0 + r) * 64 + k0 + c];
            Qs[c + 0][r] = v.x; Qs[c + 1][r] = v.y;
            Qs[c + 2][r] = v.z; Qs[c + 3][r] = v.w;
            float4 w = *(const float4*)&Km[(size_t)(col0 + r) * 64 + k0 + c];
            Ks[c + 0][r] = w.x; Ks[c + 1][r] = w.y;
            Ks[c + 2][r] = w.z; Ks[c + 3][r] = w.w;
        }
        __syncthreads();
#pragma unroll
        for (int k = 0; k < 32; k++) {
            float4 a0 = *(const float4*)&Qs[k][ty * 8];
            float4 a1 = *(const float4*)&Qs[k][ty * 8 + 4];
            float4 b0 = *(const float4*)&Ks[k][tx * 4];
            float4 b1 = *(const float4*)&Ks[k][64 + tx * 4];
            float a[8] = {a0.x, a0.y, a0.z, a0.w, a1.x, a1.y, a1.z, a1.w};
            float b[8] = {b0.x, b0.y, b0.z, b0.w, b1.x, b1.y, b1.z, b1.w};
#pragma unroll
            for (int i = 0; i < 8; i++)
#pragma unroll
                for (int j = 0; j < 8; j++)
                    acc[i][j] = fmaf(a[i], b[j], acc[i][j]);
        }
        __syncthreads();
    }

    const float scale = 0.125f; // 1/sqrt(64)
    const size_t base = (size_t)bh * LQ_ * LK_;
    const int n0 = col0 + tx * 4;
#pragma unroll
    for (int i = 0; i < 8; i++) {
        int row = row0 + ty * 8 + i;
        float4 s0 = make_float4(acc[i][0] * scale, acc[i][1] * scale,
                                acc[i][2] * scale, acc[i][3] * scale);
        float4 s1 = make_float4(acc[i][4] * scale, acc[i][5] * scale,
                                acc[i][6] * scale, acc[i][7] * scale);
        *(float4*)&S[base + (size_t)row * LK_ + n0] = s0;
        *(float4*)&S[base + (size_t)row * LK_ + n0 + 64] = s1;
    }
}

// ============================================================================
// Row softmax in place: one block per row of 2048, 256 threads x 8 elements.
// ============================================================================
__global__ void __launch_bounds__(256) softmax_kernel(float* __restrict__ A)
{
    const size_t row = blockIdx.x;
    float* p = A + row * (size_t)LK_;
    const int tid = threadIdx.x;
    const int lane = tid & 31, wid = tid >> 5;

    float4 v0 = *(const float4*)&p[tid * 8];
    float4 v1 = *(const float4*)&p[tid * 8 + 4];

    float m = fmaxf(fmaxf(fmaxf(v0.x, v0.y), fmaxf(v0.z, v0.w)),
                    fmaxf(fmaxf(v1.x, v1.y), fmaxf(v1.z, v1.w)));
#pragma unroll
    for (int o = 16; o; o >>= 1) m = fmaxf(m, __shfl_xor_sync(0xffffffffu, m, o));

    __shared__ float red[8];
    if (lane == 0) red[wid] = m;
    __syncthreads();
    float bm = red[0];
#pragma unroll
    for (int i = 1; i < 8; i++) bm = fmaxf(bm, red[i]);

    v0.x = __expf(v0.x - bm); v0.y = __expf(v0.y - bm);
    v0.z = __expf(v0.z - bm); v0.w = __expf(v0.w - bm);
    v1.x = __expf(v1.x - bm); v1.y = __expf(v1.y - bm);
    v1.z = __expf(v1.z - bm); v1.w = __expf(v1.w - bm);

    float s = (v0.x + v0.y) + (v0.z + v0.w) + (v1.x + v1.y) + (v1.z + v1.w);
#pragma unroll
    for (int o = 16; o; o >>= 1) s += __shfl_xor_sync(0xffffffffu, s, o);

    __syncthreads();
    if (lane == 0) red[wid] = s;
    __syncthreads();
    float bs = 0.f;
#pragma unroll
    for (int i = 0; i < 8; i++) bs += red[i];
    float inv = 1.0f / bs;

    v0.x *= inv; v0.y *= inv; v0.z *= inv; v0.w *= inv;
    v1.x *= inv; v1.y *= inv; v1.z *= inv; v1.w *= inv;
    *(float4*)&p[tid * 8] = v0;
    *(float4*)&p[tid * 8 + 4] = v1;
}

// ============================================================================
// Context: ctx[b, q, h*64+e] = sum_k P[bh,q,k] * V[bh,k,e]
// Per (b,h): 2048x64x2048. Tile 128x64x32, 256 thr, micro 8x4.
// ============================================================================
__global__ void __launch_bounds__(256) ctx_kernel(const float* __restrict__ P)
{
    __shared__ float As[32][132];
    __shared__ float Bs[32][68];
    const int tid = threadIdx.x;
    const int tx = tid & 15;
    const int ty = tid >> 4;
    const int bh = blockIdx.z;
    const int row0 = blockIdx.y * 128;
    const float* Pb = P + (size_t)bh * LQ_ * LK_;
    const float* V = g_V + (size_t)bh * LK_ * DV_;

    float acc[8][4];
#pragma unroll
    for (int i = 0; i < 8; i++)
#pragma unroll
        for (int j = 0; j < 4; j++) acc[i][j] = 0.f;

    for (int k0 = 0; k0 < LK_; k0 += 32) {
#pragma unroll
        for (int i = 0; i < 4; i++) {
            int idx = tid + i * 256;
            int r = idx >> 3;
            int c = (idx & 7) << 2;
            float4 v = *(const float4*)&Pb[(size_t)(row0 + r) * LK_ + k0 + c];
            As[c + 0][r] = v.x; As[c + 1][r] = v.y;
            As[c + 2][r] = v.z; As[c + 3][r] = v.w;
        }
#pragma unroll
        for (int i = 0; i < 2; i++) {
            int idx = tid + i * 256;
            int br = idx >> 4;
            int bc = (idx & 15) << 2;
            *(float4*)&Bs[br][bc] = *(const float4*)&V[(size_t)(k0 + br) * 64 + bc];
        }
        __syncthreads();
#pragma unroll
        for (int k = 0; k < 32; k++) {
            float4 a0 = *(const float4*)&As[k][ty * 8];
            float4 a1 = *(const float4*)&As[k][ty * 8 + 4];
            float4 b = *(const float4*)&Bs[k][tx * 4];
            float a[8] = {a0.x, a0.y, a0.z, a0.w, a1.x, a1.y, a1.z, a1.w};
            float bb[4] = {b.x, b.y, b.z, b.w};
#pragma unroll
            for (int i = 0; i < 8; i++)
#pragma unroll
                for (int j = 0; j < 4; j++)
                    acc[i][j] = fmaf(a[i], bb[j], acc[i][j]);
        }
        __syncthreads();
    }

    const int b = bh >> 4, h = bh & 15;
#pragma unroll
    for (int i = 0; i < 8; i++) {
        int qrow = row0 + ty * 8 + i;
        float4 s = make_float4(acc[i][0], acc[i][1], acc[i][2], acc[i][3]);
        *(float4*)&g_ctx[(size_t)(b * 2048 + qrow) * 1024 + h * 64 + tx * 4] = s;
    }
}

// ============================================================================
// Output projection: out[r, n] = sum_c ctx[r, c] * wo[c, n]; M=8192,N=K=1024.
// ============================================================================
__global__ void __launch_bounds__(256) outproj_kernel(const float* __restrict__ W,
                                                      float* __restrict__ C)
{
    __shared__ float As[16][132];
    __shared__ float Bs[16][132];
    const int tid = threadIdx.x;
    const int tx = tid & 15;
    const int ty = tid >> 4;
    const int row0 = blockIdx.y * 128;
    const int col0 = blockIdx.x * 128;

    float acc[8][8];
#pragma unroll
    for (int i = 0; i < 8; i++)
#pragma unroll
        for (int j = 0; j < 8; j++) acc[i][j] = 0.f;

    for (int k0 = 0; k0 < DM_; k0 += 16) {
#pragma unroll
        for (int i = 0; i < 2; i++) {
            int idx = tid + i * 256;
            int ar = idx >> 2;
            int ac = (idx & 3) << 2;
            float4 v = *(const float4*)&g_ctx[(size_t)(row0 + ar) * DM_ + k0 + ac];
            As[ac + 0][ar] = v.x; As[ac + 1][ar] = v.y;
            As[ac + 2][ar] = v.z; As[ac + 3][ar] = v.w;
        }
#pragma unroll
        for (int i = 0; i < 2; i++) {
            int idx = tid + i * 256;
            int br = idx >> 5;
            int bc = (idx & 31) << 2;
            float4 v = *(const float4*)&W[(size_t)(k0 + br) * DM_ + col0 + bc];
            *(float4*)&Bs[br][bc] = v;
        }
        __syncthreads();
#pragma unroll
        for (int k = 0; k < 16; k++) {
            float4 a0 = *(const float4*)&As[k][ty * 8];
            float4 a1 = *(const float4*)&As[k][ty * 8 + 4];
            float4 b0 = *(const float4*)&Bs[k][tx * 4];
            float4 b1 = *(const float4*)&Bs[k][64 + tx * 4];
            float a[8] = {a0.x, a0.y, a0.z, a0.w, a1.x, a1.y, a1.z, a1.w};
            float b[8] = {b0.x, b0.y, b0.z, b0.w, b1.x, b1.y, b1.z, b1.w};
#pragma unroll
            for (int i = 0; i < 8; i++)
#pragma unroll
                for (int j = 0; j < 8; j++)
                    acc[i][j] = fmaf(a[i], b[j], acc[i][j]);
        }
        __syncthreads();
    }

#pragma unroll
    for (int i = 0; i < 8; i++) {
        int row = row0 + ty * 8 + i;
        float4 s0 = make_float4(acc[i][0], acc[i][1], acc[i][2], acc[i][3]);
        float4 s1 = make_float4(acc[i][4], acc[i][5], acc[i][6], acc[i][7]);
        *(float4*)&C[(size_t)row * DM_ + col0 + tx * 4] = s0;
        *(float4*)&C[(size_t)row * DM_ + col0 + 64 + tx * 4] = s1;
    }
}

// ============================================================================
// Launch
// ============================================================================
extern "C" void kernel_launch(void* const* d_in, const int* in_sizes, int n_in,
                              void* d_out, int out_size)
{
    const float* q  = (const float*)d_in[0];
    const float* k  = (const float*)d_in[1];
    const float* v  = (const float*)d_in[2];
    const float* wq = (const float*)d_in[3];
    const float* wk = (const float*)d_in[4];
    const float* wv = (const float*)d_in[5];
    const float* wo = (const float*)d_in[6];
    float* out = (float*)d_out;

    const long long OUT_E = (long long)B_ * LQ_ * DM_;        // 8,388,608
    const long long ATT_E = (long long)B_ * H_ * LQ_ * LK_;   // 268,435,456

    float* attn;
    if ((long long)out_size >= OUT_E + ATT_E) {
        attn = out + OUT_E;                 // tuple output: [out, attn]
    } else {
        void* p = nullptr;
        cudaGetSymbolAddress(&p, g_attn_fb);
        attn = (float*)p;
    }

    float *gq, *gk, *gv;
    cudaGetSymbolAddress((void**)&gq, g_Q);
    cudaGetSymbolAddress((void**)&gk, g_K);
    cudaGetSymbolAddress((void**)&gv, g_V);

    dim3 t(256);
    proj_kernel<<<dim3(8, 64), t>>>(q, wq, gq);
    proj_kernel<<<dim3(8, 64), t>>>(k, wk, gk);
    proj_kernel<<<dim3(8, 64), t>>>(v, wv, gv);
    scores_kernel<<<dim3(16, 16, 64), t>>>(attn);
    softmax_kernel<<<dim3(B_ * H_ * LQ_), t>>>(attn);
    ctx_kernel<<<dim3(1, 16, 64), t>>>(attn);
    outproj_kernel<<<dim3(8, 64), t>>>(wo, out);
}

// round 8
// speedup vs baseline: 1.1683x; 1.1683x over previous
#include <cuda_runtime.h>
#include <cuda_bf16.h>
#include <cstdint>

#define B_  4
#define H_  16
#define LQ_ 2048
#define LK_ 2048
#define DM_ 1024
#define DK_ 64
#define DV_ 64

// ---- device scratch (allocation-free rule: __device__ globals) ----
__device__ float g_Q[B_ * H_ * LQ_ * DK_];        // (B,H,LQ,DK)
__device__ float g_K[B_ * H_ * LK_ * DK_];        // (B,H,LK,DK)
__device__ float g_V[B_ * H_ * LK_ * DV_];        // (B,H,LK,DV)
__device__ float g_ctx[B_ * LQ_ * H_ * DV_];      // (B,LQ,H*DV)
__device__ float g_attn_fb[B_ * H_ * LQ_ * LK_];  // fallback attn scratch

// ============================================================================
// Helpers: bf16 2-way split + m16n8k16 bf16 MMA (HMMA, valid on compute_103)
// ============================================================================
__device__ __forceinline__ void split2(float x, unsigned short& h, unsigned short& l) {
    __nv_bfloat16 bh = __float2bfloat16(x);
    float r = x - __bfloat162float(bh);
    __nv_bfloat16 bl = __float2bfloat16(r);
    h = __bfloat16_as_ushort(bh);
    l = __bfloat16_as_ushort(bl);
}

__device__ __forceinline__ void mma16816(float* c, const uint32_t* a, const uint32_t* b) {
    asm volatile(
        "mma.sync.aligned.m16n8k16.row.col.f32.bf16.bf16.f32 "
        "{%0,%1,%2,%3}, {%4,%5,%6,%7}, {%8,%9}, {%0,%1,%2,%3};"
        : "+f"(c[0]), "+f"(c[1]), "+f"(c[2]), "+f"(c[3])
        : "r"(a[0]), "r"(a[1]), "r"(a[2]), "r"(a[3]), "r"(b[0]), "r"(b[1]));
}

// Load an A fragment (m16 x k16) from smem tile T[128][16] at row r0, lane decomp
#define LOAD_AFRAG(dst, T, r0, gid, tig)                         \
    do {                                                         \
        (dst)[0] = *(const uint32_t*)&(T)[(r0) + (gid)][2 * (tig)];      \
        (dst)[1] = *(const uint32_t*)&(T)[(r0) + (gid) + 8][2 * (tig)];  \
        (dst)[2] = *(const uint32_t*)&(T)[(r0) + (gid)][2 * (tig) + 8];  \
        (dst)[3] = *(const uint32_t*)&(T)[(r0) + (gid) + 8][2 * (tig) + 8]; \
    } while (0)

#define LOAD_BFRAG(dst, T, n, tig)                               \
    do {                                                         \
        (dst)[0] = *(const uint32_t*)&(T)[n][2 * (tig)];         \
        (dst)[1] = *(const uint32_t*)&(T)[n][2 * (tig) + 8];     \
    } while (0)

// ============================================================================
// Projection: Out[b,h,l,e] = sum_d A[b*LQ+l, d] * W[h,d,e]
// GEMM M=8192, N=1024, K=1024.  Block 128x128, 8 warps (4m x 2n), k-step 16.
// Split-bf16, 3 MMA products per fragment pair.
// ============================================================================
__global__ void __launch_bounds__(256) proj_tc(const float* __restrict__ A,
                                               const float* __restrict__ W,
                                               float* __restrict__ Out)
{
    __shared__ unsigned short Ah[128][16], Al[128][16];
    __shared__ unsigned short Bh[128][16], Bl[128][16];

    const int tid = threadIdx.x;
    const int wid = tid >> 5;
    const int lane = tid & 31;
    const int gid = lane >> 2;
    const int tig = lane & 3;
    const int wm = wid & 3;       // m-offset = wm*32
    const int wn = wid >> 2;      // n-offset = wn*64
    const int row0 = blockIdx.y * 128;
    const int col0 = blockIdx.x * 128;

    float acc[2][8][4];
#pragma unroll
    for (int i = 0; i < 2; i++)
#pragma unroll
        for (int j = 0; j < 8; j++)
#pragma unroll
            for (int t = 0; t < 4; t++) acc[i][j][t] = 0.f;

    // B-fill mapping: thread -> fixed n, 8 strided k's
    const int bn = tid & 127;
    const int bkg = (tid >> 7) << 3;  // 0 or 8
    const int ng = col0 + bn;
    const int bh_ = ng >> 6, be = ng & 63;

    for (int k0 = 0; k0 < DM_; k0 += 16) {
        // A tile: 128x16 from A (row stride DM_)
#pragma unroll
        for (int i = 0; i < 2; i++) {
            int idx = tid + i * 256;
            int r = idx >> 2;
            int c = (idx & 3) << 2;
            float4 v = *(const float4*)&A[(size_t)(row0 + r) * DM_ + k0 + c];
            ushort4 h, l;
            split2(v.x, h.x, l.x); split2(v.y, h.y, l.y);
            split2(v.z, h.z, l.z); split2(v.w, h.w, l.w);
            *(ushort4*)&Ah[r][c] = h;
            *(ushort4*)&Al[r][c] = l;
        }
        // B tile: transpose of W: Bs[n][k] = W[h, k0+k, e]
        {
            const float* wp = &W[((size_t)(bh_ << 10) + k0 + bkg) * 64 + be];
#pragma unroll
            for (int j = 0; j < 8; j++)
                split2(wp[(size_t)j * 64], Bh[bn][bkg + j], Bl[bn][bkg + j]);
        }
        __syncthreads();

        uint32_t ah[2][4], al[2][4];
#pragma unroll
        for (int mi = 0; mi < 2; mi++) {
            LOAD_AFRAG(ah[mi], Ah, wm * 32 + mi * 16, gid, tig);
            LOAD_AFRAG(al[mi], Al, wm * 32 + mi * 16, gid, tig);
        }
#pragma unroll
        for (int ni = 0; ni < 8; ni++) {
            int n = wn * 64 + ni * 8 + gid;
            uint32_t bhf[2], blf[2];
            LOAD_BFRAG(bhf, Bh, n, tig);
            LOAD_BFRAG(blf, Bl, n, tig);
#pragma unroll
            for (int mi = 0; mi < 2; mi++) {
                mma16816(acc[mi][ni], ah[mi], bhf);
                mma16816(acc[mi][ni], ah[mi], blf);
                mma16816(acc[mi][ni], al[mi], bhf);
            }
        }
        __syncthreads();
    }

    // Epilogue: write fp32 to (B,H,L,64)
#pragma unroll
    for (int mi = 0; mi < 2; mi++) {
#pragma unroll
        for (int ni = 0; ni < 8; ni++) {
            int n = col0 + wn * 64 + ni * 8 + 2 * tig;
            int hh = n >> 6, e = n & 63;
            int row = row0 + wm * 32 + mi * 16 + gid;
            int b = row >> 11, l = row & 2047;
            size_t base = (size_t)((b << 4) + hh) * 2048 + l;
            *(float2*)&Out[base * 64 + e] = make_float2(acc[mi][ni][0], acc[mi][ni][1]);
            row += 8;
            b = row >> 11; l = row & 2047;
            base = (size_t)((b << 4) + hh) * 2048 + l;
            *(float2*)&Out[base * 64 + e] = make_float2(acc[mi][ni][2], acc[mi][ni][3]);
        }
    }
}

// ============================================================================
// Scores: S[bh,q,k] = 0.125 * sum_e Q[bh,q,e]*K[bh,k,e]
// Per bh: M=2048, N=2048, K=64.  Block 128x128, k-step 16 (4 steps).
// B operand is K rows (n = key pos, k = e) -> no transpose needed.
// ============================================================================
__global__ void __launch_bounds__(256) scores_tc(const float* __restrict__ Q,
                                                 const float* __restrict__ K,
                                                 float* __restrict__ S)
{
    __shared__ unsigned short Ah[128][16], Al[128][16];
    __shared__ unsigned short Bh[128][16], Bl[128][16];

    const int tid = threadIdx.x;
    const int wid = tid >> 5;
    const int lane = tid & 31;
    const int gid = lane >> 2;
    const int tig = lane & 3;
    const int wm = wid & 3;
    const int wn = wid >> 2;
    const int bh = blockIdx.z;
    const int row0 = blockIdx.y * 128;
    const int col0 = blockIdx.x * 128;
    const float* Qb = Q + (size_t)bh * LQ_ * DK_;
    const float* Kb = K + (size_t)bh * LK_ * DK_;

    float acc[2][8][4];
#pragma unroll
    for (int i = 0; i < 2; i++)
#pragma unroll
        for (int j = 0; j < 8; j++)
#pragma unroll
            for (int t = 0; t < 4; t++) acc[i][j][t] = 0.f;

    for (int k0 = 0; k0 < DK_; k0 += 16) {
#pragma unroll
        for (int i = 0; i < 2; i++) {
            int idx = tid + i * 256;
            int r = idx >> 2;
            int c = (idx & 3) << 2;
            float4 v = *(const float4*)&Qb[(size_t)(row0 + r) * 64 + k0 + c];
            ushort4 h, l;
            split2(v.x, h.x, l.x); split2(v.y, h.y, l.y);
            split2(v.z, h.z, l.z); split2(v.w, h.w, l.w);
            *(ushort4*)&Ah[r][c] = h;
            *(ushort4*)&Al[r][c] = l;
            float4 w = *(const float4*)&Kb[(size_t)(col0 + r) * 64 + k0 + c];
            split2(w.x, h.x, l.x); split2(w.y, h.y, l.y);
            split2(w.z, h.z, l.z); split2(w.w, h.w, l.w);
            *(ushort4*)&Bh[r][c] = h;
            *(ushort4*)&Bl[r][c] = l;
        }
        __syncthreads();

        uint32_t ah[2][4], al[2][4];
#pragma unroll
        for (int mi = 0; mi < 2; mi++) {
            LOAD_AFRAG(ah[mi], Ah, wm * 32 + mi * 16, gid, tig);
            LOAD_AFRAG(al[mi], Al, wm * 32 + mi * 16, gid, tig);
        }
#pragma unroll
        for (int ni = 0; ni < 8; ni++) {
            int n = wn * 64 + ni * 8 + gid;
            uint32_t bhf[2], blf[2];
            LOAD_BFRAG(bhf, Bh, n, tig);
            LOAD_BFRAG(blf, Bl, n, tig);
#pragma unroll
            for (int mi = 0; mi < 2; mi++) {
                mma16816(acc[mi][ni], ah[mi], bhf);
                mma16816(acc[mi][ni], ah[mi], blf);
                mma16816(acc[mi][ni], al[mi], bhf);
            }
        }
        __syncthreads();
    }

    const float scale = 0.125f;
    float* Sb = S + (size_t)bh * LQ_ * LK_;
#pragma unroll
    for (int mi = 0; mi < 2; mi++) {
#pragma unroll
        for (int ni = 0; ni < 8; ni++) {
            int row = row0 + wm * 32 + mi * 16 + gid;
            int col = col0 + wn * 64 + ni * 8 + 2 * tig;
            *(float2*)&Sb[(size_t)row * LK_ + col] =
                make_float2(acc[mi][ni][0] * scale, acc[mi][ni][1] * scale);
            *(float2*)&Sb[(size_t)(row + 8) * LK_ + col] =
                make_float2(acc[mi][ni][2] * scale, acc[mi][ni][3] * scale);
        }
    }
}

// ============================================================================
// Row softmax in place: one block per row of 2048, 256 threads x 8 elements.
// ============================================================================
__global__ void __launch_bounds__(256) softmax_kernel(float* __restrict__ A)
{
    const size_t row = blockIdx.x;
    float* p = A + row * (size_t)LK_;
    const int tid = threadIdx.x;
    const int lane = tid & 31, wid = tid >> 5;

    float4 v0 = *(const float4*)&p[tid * 8];
    float4 v1 = *(const float4*)&p[tid * 8 + 4];

    float m = fmaxf(fmaxf(fmaxf(v0.x, v0.y), fmaxf(v0.z, v0.w)),
                    fmaxf(fmaxf(v1.x, v1.y), fmaxf(v1.z, v1.w)));
#pragma unroll
    for (int o = 16; o; o >>= 1) m = fmaxf(m, __shfl_xor_sync(0xffffffffu, m, o));

    __shared__ float red[8];
    if (lane == 0) red[wid] = m;
    __syncthreads();
    float bm = red[0];
#pragma unroll
    for (int i = 1; i < 8; i++) bm = fmaxf(bm, red[i]);

    v0.x = __expf(v0.x - bm); v0.y = __expf(v0.y - bm);
    v0.z = __expf(v0.z - bm); v0.w = __expf(v0.w - bm);
    v1.x = __expf(v1.x - bm); v1.y = __expf(v1.y - bm);
    v1.z = __expf(v1.z - bm); v1.w = __expf(v1.w - bm);

    float s = (v0.x + v0.y) + (v0.z + v0.w) + (v1.x + v1.y) + (v1.z + v1.w);
#pragma unroll
    for (int o = 16; o; o >>= 1) s += __shfl_xor_sync(0xffffffffu, s, o);

    __syncthreads();
    if (lane == 0) red[wid] = s;
    __syncthreads();
    float bs = 0.f;
#pragma unroll
    for (int i = 0; i < 8; i++) bs += red[i];
    float inv = 1.0f / bs;

    v0.x *= inv; v0.y *= inv; v0.z *= inv; v0.w *= inv;
    v1.x *= inv; v1.y *= inv; v1.z *= inv; v1.w *= inv;
    *(float4*)&p[tid * 8] = v0;
    *(float4*)&p[tid * 8 + 4] = v1;
}

// ============================================================================
// Context: ctx[b,q,h*64+e] = sum_k P[bh,q,k] * V[bh,k,e]
// Per bh: M=2048, N=64, K=2048.  Block 128x64, 8 warps (warp = 16m x 64n),
// k-step 16 (128 steps).
// ============================================================================
__global__ void __launch_bounds__(256) ctx_tc(const float* __restrict__ P,
                                              const float* __restrict__ V)
{
    __shared__ unsigned short Ah[128][16], Al[128][16];
    __shared__ unsigned short Bh[64][16], Bl[64][16];

    const int tid = threadIdx.x;
    const int wid = tid >> 5;
    const int lane = tid & 31;
    const int gid = lane >> 2;
    const int tig = lane & 3;
    const int bh = blockIdx.z;
    const int row0 = blockIdx.y * 128;
    const float* Pb = P + (size_t)bh * LQ_ * LK_;
    const float* Vb = V + (size_t)bh * LK_ * DV_;

    float acc[8][4];
#pragma unroll
    for (int j = 0; j < 8; j++)
#pragma unroll
        for (int t = 0; t < 4; t++) acc[j][t] = 0.f;

    // B-fill mapping: thread -> fixed n (0..63), 4 strided k's
    const int bn = tid & 63;
    const int bkg = (tid >> 6) << 2;  // 0,4,8,12

    for (int k0 = 0; k0 < LK_; k0 += 16) {
        // A tile: 128x16 from P (row stride LK_)
#pragma unroll
        for (int i = 0; i < 2; i++) {
            int idx = tid + i * 256;
            int r = idx >> 2;
            int c = (idx & 3) << 2;
            float4 v = *(const float4*)&Pb[(size_t)(row0 + r) * LK_ + k0 + c];
            ushort4 h, l;
            split2(v.x, h.x, l.x); split2(v.y, h.y, l.y);
            split2(v.z, h.z, l.z); split2(v.w, h.w, l.w);
            *(ushort4*)&Ah[r][c] = h;
            *(ushort4*)&Al[r][c] = l;
        }
        // B tile: V^T : Bs[e][k] = V[k0+k][e]
        {
            const float* vp = &Vb[(size_t)(k0 + bkg) * 64 + bn];
#pragma unroll
            for (int j = 0; j < 4; j++)
                split2(vp[(size_t)j * 64], Bh[bn][bkg + j], Bl[bn][bkg + j]);
        }
        __syncthreads();

        uint32_t ah[4], al[4];
        LOAD_AFRAG(ah, Ah, wid * 16, gid, tig);
        LOAD_AFRAG(al, Al, wid * 16, gid, tig);
#pragma unroll
        for (int ni = 0; ni < 8; ni++) {
            int n = ni * 8 + gid;
            uint32_t bhf[2], blf[2];
            LOAD_BFRAG(bhf, Bh, n, tig);
            LOAD_BFRAG(blf, Bl, n, tig);
            mma16816(acc[ni], ah, bhf);
            mma16816(acc[ni], ah, blf);
            mma16816(acc[ni], al, bhf);
        }
        __syncthreads();
    }

    const int b = bh >> 4, hh = bh & 15;
#pragma unroll
    for (int ni = 0; ni < 8; ni++) {
        int row = row0 + wid * 16 + gid;
        int col = hh * 64 + ni * 8 + 2 * tig;
        *(float2*)&g_ctx[(size_t)(b * 2048 + row) * 1024 + col] =
            make_float2(acc[ni][0], acc[ni][1]);
        *(float2*)&g_ctx[(size_t)(b * 2048 + row + 8) * 1024 + col] =
            make_float2(acc[ni][2], acc[ni][3]);
    }
}

// ============================================================================
// Output projection: out[r,n] = sum_c ctx[r,c] * wo[c,n]; M=8192, N=K=1024.
// Block 128x128, k-step 16.
// ============================================================================
__global__ void __launch_bounds__(256) outproj_tc(const float* __restrict__ W,
                                                  float* __restrict__ C)
{
    __shared__ unsigned short Ah[128][16], Al[128][16];
    __shared__ unsigned short Bh[128][16], Bl[128][16];

    const int tid = threadIdx.x;
    const int wid = tid >> 5;
    const int lane = tid & 31;
    const int gid = lane >> 2;
    const int tig = lane & 3;
    const int wm = wid & 3;
    const int wn = wid >> 2;
    const int row0 = blockIdx.y * 128;
    const int col0 = blockIdx.x * 128;

    float acc[2][8][4];
#pragma unroll
    for (int i = 0; i < 2; i++)
#pragma unroll
        for (int j = 0; j < 8; j++)
#pragma unroll
            for (int t = 0; t < 4; t++) acc[i][j][t] = 0.f;

    const int bn = tid & 127;
    const int bkg = (tid >> 7) << 3;

    for (int k0 = 0; k0 < DM_; k0 += 16) {
#pragma unroll
        for (int i = 0; i < 2; i++) {
            int idx = tid + i * 256;
            int r = idx >> 2;
            int c = (idx & 3) << 2;
            float4 v = *(const float4*)&g_ctx[(size_t)(row0 + r) * DM_ + k0 + c];
            ushort4 h, l;
            split2(v.x, h.x, l.x); split2(v.y, h.y, l.y);
            split2(v.z, h.z, l.z); split2(v.w, h.w, l.w);
            *(ushort4*)&Ah[r][c] = h;
            *(ushort4*)&Al[r][c] = l;
        }
        {
            const float* wp = &W[(size_t)(k0 + bkg) * DM_ + col0 + bn];
#pragma unroll
            for (int j = 0; j < 8; j++)
                split2(wp[(size_t)j * DM_], Bh[bn][bkg + j], Bl[bn][bkg + j]);
        }
        __syncthreads();

        uint32_t ah[2][4], al[2][4];
#pragma unroll
        for (int mi = 0; mi < 2; mi++) {
            LOAD_AFRAG(ah[mi], Ah, wm * 32 + mi * 16, gid, tig);
            LOAD_AFRAG(al[mi], Al, wm * 32 + mi * 16, gid, tig);
        }
#pragma unroll
        for (int ni = 0; ni < 8; ni++) {
            int n = wn * 64 + ni * 8 + gid;
            uint32_t bhf[2], blf[2];
            LOAD_BFRAG(bhf, Bh, n, tig);
            LOAD_BFRAG(blf, Bl, n, tig);
#pragma unroll
            for (int mi = 0; mi < 2; mi++) {
                mma16816(acc[mi][ni], ah[mi], bhf);
                mma16816(acc[mi][ni], ah[mi], blf);
                mma16816(acc[mi][ni], al[mi], bhf);
            }
        }
        __syncthreads();
    }

#pragma unroll
    for (int mi = 0; mi < 2; mi++) {
#pragma unroll
        for (int ni = 0; ni < 8; ni++) {
            int row = row0 + wm * 32 + mi * 16 + gid;
            int col = col0 + wn * 64 + ni * 8 + 2 * tig;
            *(float2*)&C[(size_t)row * DM_ + col] =
                make_float2(acc[mi][ni][0], acc[mi][ni][1]);
            *(float2*)&C[(size_t)(row + 8) * DM_ + col] =
                make_float2(acc[mi][ni][2], acc[mi][ni][3]);
        }
    }
}

// ============================================================================
// Launch
// ============================================================================
extern "C" void kernel_launch(void* const* d_in, const int* in_sizes, int n_in,
                              void* d_out, int out_size)
{
    const float* q  = (const float*)d_in[0];
    const float* k  = (const float*)d_in[1];
    const float* v  = (const float*)d_in[2];
    const float* wq = (const float*)d_in[3];
    const float* wk = (const float*)d_in[4];
    const float* wv = (const float*)d_in[5];
    const float* wo = (const float*)d_in[6];
    float* out = (float*)d_out;

    const long long OUT_E = (long long)B_ * LQ_ * DM_;        // 8,388,608
    const long long ATT_E = (long long)B_ * H_ * LQ_ * LK_;   // 268,435,456

    float* attn;
    if ((long long)out_size >= OUT_E + ATT_E) {
        attn = out + OUT_E;                 // tuple output: [out, attn]
    } else {
        void* p = nullptr;
        cudaGetSymbolAddress(&p, g_attn_fb);
        attn = (float*)p;
    }

    float *gq, *gk, *gv;
    cudaGetSymbolAddress((void**)&gq, g_Q);
    cudaGetSymbolAddress((void**)&gk, g_K);
    cudaGetSymbolAddress((void**)&gv, g_V);

    dim3 t(256);
    proj_tc<<<dim3(8, 64), t>>>(q, wq, gq);
    proj_tc<<<dim3(8, 64), t>>>(k, wk, gk);
    proj_tc<<<dim3(8, 64), t>>>(v, wv, gv);
    scores_tc<<<dim3(16, 16, 64), t>>>(gq, gk, attn);
    softmax_kernel<<<dim3(B_ * H_ * LQ_), t>>>(attn);
    ctx_tc<<<dim3(1, 16, 64), t>>>(attn, gv);
    outproj_tc<<<dim3(8, 64), t>>>(wo, out);
}

// round 9
// speedup vs baseline: 1.2865x; 1.1012x over previous
#include <cuda_runtime.h>
#include <cuda_bf16.h>
#include <cstdint>

#define B_  4
#define H_  16
#define LQ_ 2048
#define LK_ 2048
#define DM_ 1024
#define DK_ 64
#define DV_ 64

// ---- device scratch (allocation-free rule: __device__ globals) ----
__device__ float g_Q[B_ * H_ * LQ_ * DK_];        // (B,H,LQ,DK)
__device__ float g_K[B_ * H_ * LK_ * DK_];        // (B,H,LK,DK)
__device__ float g_V[B_ * H_ * LK_ * DV_];        // (B,H,LK,DV)
__device__ float g_ctx[B_ * LQ_ * H_ * DV_];      // (B,LQ,H*DV)
__device__ float g_attn_fb[B_ * H_ * LQ_ * LK_];  // fallback attn scratch

// ============================================================================
// Helpers: bf16 2-way split + m16n8k16 bf16 MMA (HMMA, valid on compute_103)
// ============================================================================
__device__ __forceinline__ void split2(float x, unsigned short& h, unsigned short& l) {
    __nv_bfloat16 bh = __float2bfloat16(x);
    float r = x - __bfloat162float(bh);
    __nv_bfloat16 bl = __float2bfloat16(r);
    h = __bfloat16_as_ushort(bh);
    l = __bfloat16_as_ushort(bl);
}

__device__ __forceinline__ void mma16816(float* c, const uint32_t* a, const uint32_t* b) {
    asm volatile(
        "mma.sync.aligned.m16n8k16.row.col.f32.bf16.bf16.f32 "
        "{%0,%1,%2,%3}, {%4,%5,%6,%7}, {%8,%9}, {%0,%1,%2,%3};"
        : "+f"(c[0]), "+f"(c[1]), "+f"(c[2]), "+f"(c[3])
        : "r"(a[0]), "r"(a[1]), "r"(a[2]), "r"(a[3]), "r"(b[0]), "r"(b[1]));
}

// Load an A fragment (m16 x k16) from smem tile T[..][16] at row r0
#define LOAD_AFRAG(dst, T, r0, gid, tig)                         \
    do {                                                         \
        (dst)[0] = *(const uint32_t*)&(T)[(r0) + (gid)][2 * (tig)];      \
        (dst)[1] = *(const uint32_t*)&(T)[(r0) + (gid) + 8][2 * (tig)];  \
        (dst)[2] = *(const uint32_t*)&(T)[(r0) + (gid)][2 * (tig) + 8];  \
        (dst)[3] = *(const uint32_t*)&(T)[(r0) + (gid) + 8][2 * (tig) + 8]; \
    } while (0)

#define LOAD_BFRAG(dst, T, n, tig)                               \
    do {                                                         \
        (dst)[0] = *(const uint32_t*)&(T)[n][2 * (tig)];         \
        (dst)[1] = *(const uint32_t*)&(T)[n][2 * (tig) + 8];     \
    } while (0)

// ============================================================================
// Projection: Out[b,h,l,e] = sum_d A[b*LQ+l, d] * W[h,d,e]
// GEMM M=8192, N=1024, K=1024.  Block 128x128, 8 warps (4m x 2n), k-step 16.
// Split-bf16, 3 MMA products, 2-stage smem double buffer + reg prefetch.
// ============================================================================
__global__ void __launch_bounds__(256) proj_tc(const float* __restrict__ A,
                                               const float* __restrict__ W,
                                               float* __restrict__ Out)
{
    __shared__ unsigned short Ah[2][128][16], Al[2][128][16];
    __shared__ unsigned short Bh[2][128][16], Bl[2][128][16];

    const int tid = threadIdx.x;
    const int wid = tid >> 5;
    const int lane = tid & 31;
    const int gid = lane >> 2;
    const int tig = lane & 3;
    const int wm = wid & 3;
    const int wn = wid >> 2;
    const int row0 = blockIdx.y * 128;
    const int col0 = blockIdx.x * 128;

    // A fill mapping
    const int ar0 = tid >> 2;
    const int ac0 = (tid & 3) << 2;
    // B fill mapping
    const int bn = tid & 127;
    const int bkg = (tid >> 7) << 3;  // 0 or 8
    const int ng = col0 + bn;
    const int bh_ = ng >> 6, be = ng & 63;
    const float* wbase = &W[(size_t)(bh_ << 10) * 64 + be];

    float acc[2][8][4];
#pragma unroll
    for (int i = 0; i < 2; i++)
#pragma unroll
        for (int j = 0; j < 8; j++)
#pragma unroll
            for (int t = 0; t < 4; t++) acc[i][j][t] = 0.f;

    float4 va[2];
    float vb[8];

    // prologue: load k0=0
#pragma unroll
    for (int i = 0; i < 2; i++)
        va[i] = *(const float4*)&A[(size_t)(row0 + ar0 + i * 64) * DM_ + ac0];
#pragma unroll
    for (int j = 0; j < 8; j++) vb[j] = wbase[(size_t)(bkg + j) * 64];
    // store stage 0
#pragma unroll
    for (int i = 0; i < 2; i++) {
        ushort4 h, l;
        split2(va[i].x, h.x, l.x); split2(va[i].y, h.y, l.y);
        split2(va[i].z, h.z, l.z); split2(va[i].w, h.w, l.w);
        *(ushort4*)&Ah[0][ar0 + i * 64][ac0] = h;
        *(ushort4*)&Al[0][ar0 + i * 64][ac0] = l;
    }
#pragma unroll
    for (int j = 0; j < 8; j++) split2(vb[j], Bh[0][bn][bkg + j], Bl[0][bn][bkg + j]);
    __syncthreads();

    const int NSTEP = DM_ / 16;  // 64
    for (int s = 0; s < NSTEP; s++) {
        const int buf = s & 1;
        const int k1 = (s + 1) * 16;
        if (s + 1 < NSTEP) {
#pragma unroll
            for (int i = 0; i < 2; i++)
                va[i] = *(const float4*)&A[(size_t)(row0 + ar0 + i * 64) * DM_ + k1 + ac0];
#pragma unroll
            for (int j = 0; j < 8; j++) vb[j] = wbase[(size_t)(k1 + bkg + j) * 64];
        }

        uint32_t ah[2][4], al[2][4];
#pragma unroll
        for (int mi = 0; mi < 2; mi++) {
            LOAD_AFRAG(ah[mi], Ah[buf], wm * 32 + mi * 16, gid, tig);
            LOAD_AFRAG(al[mi], Al[buf], wm * 32 + mi * 16, gid, tig);
        }
#pragma unroll
        for (int ni = 0; ni < 8; ni++) {
            int n = wn * 64 + ni * 8 + gid;
            uint32_t bhf[2], blf[2];
            LOAD_BFRAG(bhf, Bh[buf], n, tig);
            LOAD_BFRAG(blf, Bl[buf], n, tig);
#pragma unroll
            for (int mi = 0; mi < 2; mi++) {
                mma16816(acc[mi][ni], ah[mi], bhf);
                mma16816(acc[mi][ni], ah[mi], blf);
                mma16816(acc[mi][ni], al[mi], bhf);
            }
        }

        if (s + 1 < NSTEP) {
            const int nb = buf ^ 1;
#pragma unroll
            for (int i = 0; i < 2; i++) {
                ushort4 h, l;
                split2(va[i].x, h.x, l.x); split2(va[i].y, h.y, l.y);
                split2(va[i].z, h.z, l.z); split2(va[i].w, h.w, l.w);
                *(ushort4*)&Ah[nb][ar0 + i * 64][ac0] = h;
                *(ushort4*)&Al[nb][ar0 + i * 64][ac0] = l;
            }
#pragma unroll
            for (int j = 0; j < 8; j++)
                split2(vb[j], Bh[nb][bn][bkg + j], Bl[nb][bn][bkg + j]);
        }
        __syncthreads();
    }

    // Epilogue: write fp32 to (B,H,L,64)
#pragma unroll
    for (int mi = 0; mi < 2; mi++) {
#pragma unroll
        for (int ni = 0; ni < 8; ni++) {
            int n = col0 + wn * 64 + ni * 8 + 2 * tig;
            int hh = n >> 6, e = n & 63;
            int row = row0 + wm * 32 + mi * 16 + gid;
            int b = row >> 11, l = row & 2047;
            size_t base = (size_t)((b << 4) + hh) * 2048 + l;
            *(float2*)&Out[base * 64 + e] = make_float2(acc[mi][ni][0], acc[mi][ni][1]);
            row += 8;
            b = row >> 11; l = row & 2047;
            base = (size_t)((b << 4) + hh) * 2048 + l;
            *(float2*)&Out[base * 64 + e] = make_float2(acc[mi][ni][2], acc[mi][ni][3]);
        }
    }
}

// ============================================================================
// Scores v2: whole-K-in-smem. CTA computes 128 q-rows x 256 k-cols for one bh.
// Dynamic smem (padded stride 72 ushorts = conflict-free frag LDS):
//   Qh[128][72], Ql[128][72], Kh[256][72], Kl[256][72]  = 108 KB
// Single __syncthreads; 2 column sub-tiles processed sequentially.
// ============================================================================
#define SC_STR 72
#define SC_QH  0
#define SC_QL  (128 * SC_STR)
#define SC_KH  (2 * 128 * SC_STR)
#define SC_KL  (2 * 128 * SC_STR + 256 * SC_STR)
#define SC_SMEM_BYTES ((2 * 128 * SC_STR + 2 * 256 * SC_STR) * 2)  // 110592

__global__ void __launch_bounds__(256) scores_tc(const float* __restrict__ Q,
                                                 const float* __restrict__ K,
                                                 float* __restrict__ S)
{
    extern __shared__ unsigned short sm[];
    unsigned short* Qh = sm + SC_QH;
    unsigned short* Ql = sm + SC_QL;
    unsigned short* Kh = sm + SC_KH;
    unsigned short* Kl = sm + SC_KL;

    const int tid = threadIdx.x;
    const int wid = tid >> 5;
    const int lane = tid & 31;
    const int gid = lane >> 2;
    const int tig = lane & 3;
    const int wm = wid & 3;
    const int wn = wid >> 2;
    const int bh = blockIdx.z;
    const int row0 = blockIdx.y * 128;
    const int col0 = blockIdx.x * 256;
    const float* Qb = Q + (size_t)bh * LQ_ * DK_;
    const float* Kb = K + (size_t)bh * LK_ * DK_;

    // Fill Q: 128 rows x 16 float4
#pragma unroll
    for (int i = 0; i < 8; i++) {
        int idx = tid + i * 256;
        int r = idx >> 4;
        int c4 = (idx & 15) << 2;
        float4 v = *(const float4*)&Qb[(size_t)(row0 + r) * 64 + c4];
        ushort4 h, l;
        split2(v.x, h.x, l.x); split2(v.y, h.y, l.y);
        split2(v.z, h.z, l.z); split2(v.w, h.w, l.w);
        *(ushort4*)&Qh[r * SC_STR + c4] = h;
        *(ushort4*)&Ql[r * SC_STR + c4] = l;
    }
    // Fill K: 256 rows x 16 float4
#pragma unroll
    for (int i = 0; i < 16; i++) {
        int idx = tid + i * 256;
        int r = idx >> 4;
        int c4 = (idx & 15) << 2;
        float4 v = *(const float4*)&Kb[(size_t)(col0 + r) * 64 + c4];
        ushort4 h, l;
        split2(v.x, h.x, l.x); split2(v.y, h.y, l.y);
        split2(v.z, h.z, l.z); split2(v.w, h.w, l.w);
        *(ushort4*)&Kh[r * SC_STR + c4] = h;
        *(ushort4*)&Kl[r * SC_STR + c4] = l;
    }
    __syncthreads();

    const float scale = 0.125f;
    float* Sb = S + (size_t)bh * LQ_ * LK_;

#pragma unroll
    for (int ct = 0; ct < 2; ct++) {
        float acc[2][8][4];
#pragma unroll
        for (int i = 0; i < 2; i++)
#pragma unroll
            for (int j = 0; j < 8; j++)
#pragma unroll
                for (int t = 0; t < 4; t++) acc[i][j][t] = 0.f;

#pragma unroll
        for (int k0 = 0; k0 < 64; k0 += 16) {
            uint32_t ah[2][4], al[2][4];
#pragma unroll
            for (int mi = 0; mi < 2; mi++) {
                int r = wm * 32 + mi * 16 + gid;
                const unsigned short* qh = &Qh[r * SC_STR + k0 + 2 * tig];
                const unsigned short* ql = &Ql[r * SC_STR + k0 + 2 * tig];
                ah[mi][0] = *(const uint32_t*)qh;
                ah[mi][1] = *(const uint32_t*)(qh + 8 * SC_STR);
                ah[mi][2] = *(const uint32_t*)(qh + 8);
                ah[mi][3] = *(const uint32_t*)(qh + 8 * SC_STR + 8);
                al[mi][0] = *(const uint32_t*)ql;
                al[mi][1] = *(const uint32_t*)(ql + 8 * SC_STR);
                al[mi][2] = *(const uint32_t*)(ql + 8);
                al[mi][3] = *(const uint32_t*)(ql + 8 * SC_STR + 8);
            }
#pragma unroll
            for (int ni = 0; ni < 8; ni++) {
                int n = ct * 128 + wn * 64 + ni * 8 + gid;
                const unsigned short* kh = &Kh[n * SC_STR + k0 + 2 * tig];
                const unsigned short* kl = &Kl[n * SC_STR + k0 + 2 * tig];
                uint32_t bhf[2], blf[2];
                bhf[0] = *(const uint32_t*)kh; bhf[1] = *(const uint32_t*)(kh + 8);
                blf[0] = *(const uint32_t*)kl; blf[1] = *(const uint32_t*)(kl + 8);
#pragma unroll
                for (int mi = 0; mi < 2; mi++) {
                    mma16816(acc[mi][ni], ah[mi], bhf);
                    mma16816(acc[mi][ni], ah[mi], blf);
                    mma16816(acc[mi][ni], al[mi], bhf);
                }
            }
        }

#pragma unroll
        for (int mi = 0; mi < 2; mi++) {
#pragma unroll
            for (int ni = 0; ni < 8; ni++) {
                int row = row0 + wm * 32 + mi * 16 + gid;
                int col = col0 + ct * 128 + wn * 64 + ni * 8 + 2 * tig;
                *(float2*)&Sb[(size_t)row * LK_ + col] =
                    make_float2(acc[mi][ni][0] * scale, acc[mi][ni][1] * scale);
                *(float2*)&Sb[(size_t)(row + 8) * LK_ + col] =
                    make_float2(acc[mi][ni][2] * scale, acc[mi][ni][3] * scale);
            }
        }
    }
}

// ============================================================================
// Row softmax in place: one block per row of 2048, 256 threads x 8 elements.
// ============================================================================
__global__ void __launch_bounds__(256) softmax_kernel(float* __restrict__ A)
{
    const size_t row = blockIdx.x;
    float* p = A + row * (size_t)LK_;
    const int tid = threadIdx.x;
    const int lane = tid & 31, wid = tid >> 5;

    float4 v0 = *(const float4*)&p[tid * 8];
    float4 v1 = *(const float4*)&p[tid * 8 + 4];

    float m = fmaxf(fmaxf(fmaxf(v0.x, v0.y), fmaxf(v0.z, v0.w)),
                    fmaxf(fmaxf(v1.x, v1.y), fmaxf(v1.z, v1.w)));
#pragma unroll
    for (int o = 16; o; o >>= 1) m = fmaxf(m, __shfl_xor_sync(0xffffffffu, m, o));

    __shared__ float red[8];
    if (lane == 0) red[wid] = m;
    __syncthreads();
    float bm = red[0];
#pragma unroll
    for (int i = 1; i < 8; i++) bm = fmaxf(bm, red[i]);

    v0.x = __expf(v0.x - bm); v0.y = __expf(v0.y - bm);
    v0.z = __expf(v0.z - bm); v0.w = __expf(v0.w - bm);
    v1.x = __expf(v1.x - bm); v1.y = __expf(v1.y - bm);
    v1.z = __expf(v1.z - bm); v1.w = __expf(v1.w - bm);

    float s = (v0.x + v0.y) + (v0.z + v0.w) + (v1.x + v1.y) + (v1.z + v1.w);
#pragma unroll
    for (int o = 16; o; o >>= 1) s += __shfl_xor_sync(0xffffffffu, s, o);

    __syncthreads();
    if (lane == 0) red[wid] = s;
    __syncthreads();
    float bs = 0.f;
#pragma unroll
    for (int i = 0; i < 8; i++) bs += red[i];
    float inv = 1.0f / bs;

    v0.x *= inv; v0.y *= inv; v0.z *= inv; v0.w *= inv;
    v1.x *= inv; v1.y *= inv; v1.z *= inv; v1.w *= inv;
    *(float4*)&p[tid * 8] = v0;
    *(float4*)&p[tid * 8 + 4] = v1;
}

// ============================================================================
// Context: ctx[b,q,h*64+e] = sum_k P[bh,q,k] * V[bh,k,e]
// Per bh: M=2048, N=64, K=2048.  Block 128x64, k-step 16 (128 steps),
// 2-stage smem double buffer + reg prefetch.
// ============================================================================
__global__ void __launch_bounds__(256) ctx_tc(const float* __restrict__ P,
                                              const float* __restrict__ V)
{
    __shared__ unsigned short Ah[2][128][16], Al[2][128][16];
    __shared__ unsigned short Bh[2][64][16], Bl[2][64][16];

    const int tid = threadIdx.x;
    const int wid = tid >> 5;
    const int lane = tid & 31;
    const int gid = lane >> 2;
    const int tig = lane & 3;
    const int bh = blockIdx.z;
    const int row0 = blockIdx.y * 128;
    const float* Pb = P + (size_t)bh * LQ_ * LK_;
    const float* Vb = V + (size_t)bh * LK_ * DV_;

    const int ar0 = tid >> 2;
    const int ac0 = (tid & 3) << 2;
    const int bn = tid & 63;
    const int bkg = (tid >> 6) << 2;  // 0,4,8,12

    float acc[8][4];
#pragma unroll
    for (int j = 0; j < 8; j++)
#pragma unroll
        for (int t = 0; t < 4; t++) acc[j][t] = 0.f;

    float4 va[2];
    float vb[4];

    // prologue k0=0
#pragma unroll
    for (int i = 0; i < 2; i++)
        va[i] = *(const float4*)&Pb[(size_t)(row0 + ar0 + i * 64) * LK_ + ac0];
#pragma unroll
    for (int j = 0; j < 4; j++) vb[j] = Vb[(size_t)(bkg + j) * 64 + bn];
#pragma unroll
    for (int i = 0; i < 2; i++) {
        ushort4 h, l;
        split2(va[i].x, h.x, l.x); split2(va[i].y, h.y, l.y);
        split2(va[i].z, h.z, l.z); split2(va[i].w, h.w, l.w);
        *(ushort4*)&Ah[0][ar0 + i * 64][ac0] = h;
        *(ushort4*)&Al[0][ar0 + i * 64][ac0] = l;
    }
#pragma unroll
    for (int j = 0; j < 4; j++) split2(vb[j], Bh[0][bn][bkg + j], Bl[0][bn][bkg + j]);
    __syncthreads();

    const int NSTEP = LK_ / 16;  // 128
    for (int s = 0; s < NSTEP; s++) {
        const int buf = s & 1;
        const int k1 = (s + 1) * 16;
        if (s + 1 < NSTEP) {
#pragma unroll
            for (int i = 0; i < 2; i++)
                va[i] = *(const float4*)&Pb[(size_t)(row0 + ar0 + i * 64) * LK_ + k1 + ac0];
#pragma unroll
            for (int j = 0; j < 4; j++) vb[j] = Vb[(size_t)(k1 + bkg + j) * 64 + bn];
        }

        uint32_t ah[4], al[4];
        LOAD_AFRAG(ah, Ah[buf], wid * 16, gid, tig);
        LOAD_AFRAG(al, Al[buf], wid * 16, gid, tig);
#pragma unroll
        for (int ni = 0; ni < 8; ni++) {
            int n = ni * 8 + gid;
            uint32_t bhf[2], blf[2];
            LOAD_BFRAG(bhf, Bh[buf], n, tig);
            LOAD_BFRAG(blf, Bl[buf], n, tig);
            mma16816(acc[ni], ah, bhf);
            mma16816(acc[ni], ah, blf);
            mma16816(acc[ni], al, bhf);
        }

        if (s + 1 < NSTEP) {
            const int nb = buf ^ 1;
#pragma unroll
            for (int i = 0; i < 2; i++) {
                ushort4 h, l;
                split2(va[i].x, h.x, l.x); split2(va[i].y, h.y, l.y);
                split2(va[i].z, h.z, l.z); split2(va[i].w, h.w, l.w);
                *(ushort4*)&Ah[nb][ar0 + i * 64][ac0] = h;
                *(ushort4*)&Al[nb][ar0 + i * 64][ac0] = l;
            }
#pragma unroll
            for (int j = 0; j < 4; j++)
                split2(vb[j], Bh[nb][bn][bkg + j], Bl[nb][bn][bkg + j]);
        }
        __syncthreads();
    }

    const int b = bh >> 4, hh = bh & 15;
#pragma unroll
    for (int ni = 0; ni < 8; ni++) {
        int row = row0 + wid * 16 + gid;
        int col = hh * 64 + ni * 8 + 2 * tig;
        *(float2*)&g_ctx[(size_t)(b * 2048 + row) * 1024 + col] =
            make_float2(acc[ni][0], acc[ni][1]);
        *(float2*)&g_ctx[(size_t)(b * 2048 + row + 8) * 1024 + col] =
            make_float2(acc[ni][2], acc[ni][3]);
    }
}

// ============================================================================
// Output projection: out[r,n] = sum_c ctx[r,c] * wo[c,n]; M=8192, N=K=1024.
// Block 128x128, k-step 16, double-buffered.
// ============================================================================
__global__ void __launch_bounds__(256) outproj_tc(const float* __restrict__ W,
                                                  float* __restrict__ C)
{
    __shared__ unsigned short Ah[2][128][16], Al[2][128][16];
    __shared__ unsigned short Bh[2][128][16], Bl[2][128][16];

    const int tid = threadIdx.x;
    const int wid = tid >> 5;
    const int lane = tid & 31;
    const int gid = lane >> 2;
    const int tig = lane & 3;
    const int wm = wid & 3;
    const int wn = wid >> 2;
    const int row0 = blockIdx.y * 128;
    const int col0 = blockIdx.x * 128;

    const int ar0 = tid >> 2;
    const int ac0 = (tid & 3) << 2;
    const int bn = tid & 127;
    const int bkg = (tid >> 7) << 3;

    float acc[2][8][4];
#pragma unroll
    for (int i = 0; i < 2; i++)
#pragma unroll
        for (int j = 0; j < 8; j++)
#pragma unroll
            for (int t = 0; t < 4; t++) acc[i][j][t] = 0.f;

    float4 va[2];
    float vb[8];

#pragma unroll
    for (int i = 0; i < 2; i++)
        va[i] = *(const float4*)&g_ctx[(size_t)(row0 + ar0 + i * 64) * DM_ + ac0];
#pragma unroll
    for (int j = 0; j < 8; j++) vb[j] = W[(size_t)(bkg + j) * DM_ + col0 + bn];
#pragma unroll
    for (int i = 0; i < 2; i++) {
        ushort4 h, l;
        split2(va[i].x, h.x, l.x); split2(va[i].y, h.y, l.y);
        split2(va[i].z, h.z, l.z); split2(va[i].w, h.w, l.w);
        *(ushort4*)&Ah[0][ar0 + i * 64][ac0] = h;
        *(ushort4*)&Al[0][ar0 + i * 64][ac0] = l;
    }
#pragma unroll
    for (int j = 0; j < 8; j++) split2(vb[j], Bh[0][bn][bkg + j], Bl[0][bn][bkg + j]);
    __syncthreads();

    const int NSTEP = DM_ / 16;  // 64
    for (int s = 0; s < NSTEP; s++) {
        const int buf = s & 1;
        const int k1 = (s + 1) * 16;
        if (s + 1 < NSTEP) {
#pragma unroll
            for (int i = 0; i < 2; i++)
                va[i] = *(const float4*)&g_ctx[(size_t)(row0 + ar0 + i * 64) * DM_ + k1 + ac0];
#pragma unroll
            for (int j = 0; j < 8; j++) vb[j] = W[(size_t)(k1 + bkg + j) * DM_ + col0 + bn];
        }

        uint32_t ah[2][4], al[2][4];
#pragma unroll
        for (int mi = 0; mi < 2; mi++) {
            LOAD_AFRAG(ah[mi], Ah[buf], wm * 32 + mi * 16, gid, tig);
            LOAD_AFRAG(al[mi], Al[buf], wm * 32 + mi * 16, gid, tig);
        }
#pragma unroll
        for (int ni = 0; ni < 8; ni++) {
            int n = wn * 64 + ni * 8 + gid;
            uint32_t bhf[2], blf[2];
            LOAD_BFRAG(bhf, Bh[buf], n, tig);
            LOAD_BFRAG(blf, Bl[buf], n, tig);
#pragma unroll
            for (int mi = 0; mi < 2; mi++) {
                mma16816(acc[mi][ni], ah[mi], bhf);
                mma16816(acc[mi][ni], ah[mi], blf);
                mma16816(acc[mi][ni], al[mi], bhf);
            }
        }

        if (s + 1 < NSTEP) {
            const int nb = buf ^ 1;
#pragma unroll
            for (int i = 0; i < 2; i++) {
                ushort4 h, l;
                split2(va[i].x, h.x, l.x); split2(va[i].y, h.y, l.y);
                split2(va[i].z, h.z, l.z); split2(va[i].w, h.w, l.w);
                *(ushort4*)&Ah[nb][ar0 + i * 64][ac0] = h;
                *(ushort4*)&Al[nb][ar0 + i * 64][ac0] = l;
            }
#pragma unroll
            for (int j = 0; j < 8; j++)
                split2(vb[j], Bh[nb][bn][bkg + j], Bl[nb][bn][bkg + j]);
        }
        __syncthreads();
    }

#pragma unroll
    for (int mi = 0; mi < 2; mi++) {
#pragma unroll
        for (int ni = 0; ni < 8; ni++) {
            int row = row0 + wm * 32 + mi * 16 + gid;
            int col = col0 + wn * 64 + ni * 8 + 2 * tig;
            *(float2*)&C[(size_t)row * DM_ + col] =
                make_float2(acc[mi][ni][0], acc[mi][ni][1]);
            *(float2*)&C[(size_t)(row + 8) * DM_ + col] =
                make_float2(acc[mi][ni][2], acc[mi][ni][3]);
        }
    }
}

// ============================================================================
// Launch
// ============================================================================
extern "C" void kernel_launch(void* const* d_in, const int* in_sizes, int n_in,
                              void* d_out, int out_size)
{
    const float* q  = (const float*)d_in[0];
    const float* k  = (const float*)d_in[1];
    const float* v  = (const float*)d_in[2];
    const float* wq = (const float*)d_in[3];
    const float* wk = (const float*)d_in[4];
    const float* wv = (const float*)d_in[5];
    const float* wo = (const float*)d_in[6];
    float* out = (float*)d_out;

    const long long OUT_E = (long long)B_ * LQ_ * DM_;        // 8,388,608
    const long long ATT_E = (long long)B_ * H_ * LQ_ * LK_;   // 268,435,456

    float* attn;
    if ((long long)out_size >= OUT_E + ATT_E) {
        attn = out + OUT_E;                 // tuple output: [out, attn]
    } else {
        void* p = nullptr;
        cudaGetSymbolAddress(&p, g_attn_fb);
        attn = (float*)p;
    }

    float *gq, *gk, *gv;
    cudaGetSymbolAddress((void**)&gq, g_Q);
    cudaGetSymbolAddress((void**)&gk, g_K);
    cudaGetSymbolAddress((void**)&gv, g_V);

    cudaFuncSetAttribute(scores_tc,
                         cudaFuncAttributeMaxDynamicSharedMemorySize, SC_SMEM_BYTES);

    dim3 t(256);
    proj_tc<<<dim3(8, 64), t>>>(q, wq, gq);
    proj_tc<<<dim3(8, 64), t>>>(k, wk, gk);
    proj_tc<<<dim3(8, 64), t>>>(v, wv, gv);
    scores_tc<<<dim3(8, 16, 64), t, SC_SMEM_BYTES>>>(gq, gk, attn);
    softmax_kernel<<<dim3(B_ * H_ * LQ_), t>>>(attn);
    ctx_tc<<<dim3(1, 16, 64), t>>>(attn, gv);
    outproj_tc<<<dim3(8, 64), t>>>(wo, out);
}

// round 13
// speedup vs baseline: 1.6572x; 1.2881x over previous
#include <cuda_runtime.h>
#include <cuda_bf16.h>
#include <cstdint>

#define B_  4
#define H_  16
#define LQ_ 2048
#define LK_ 2048
#define DM_ 1024
#define DK_ 64
#define DV_ 64

// ---- device scratch (allocation-free rule: __device__ globals) ----
__device__ float g_Q[B_ * H_ * LQ_ * DK_];        // (B,H,LQ,DK)
__device__ float g_K[B_ * H_ * LK_ * DK_];        // (B,H,LK,DK)
__device__ float g_V[B_ * H_ * LK_ * DV_];        // (B,H,LK,DV)
__device__ float g_ctx[B_ * LQ_ * H_ * DV_];      // (B,LQ,H*DV)
__device__ float g_attn_fb[B_ * H_ * LQ_ * LK_];  // fallback attn scratch

// ============================================================================
// Helpers
// ============================================================================
__device__ __forceinline__ void split2(float x, unsigned short& h, unsigned short& l) {
    __nv_bfloat16 bh = __float2bfloat16(x);
    float r = x - __bfloat162float(bh);
    __nv_bfloat16 bl = __float2bfloat16(r);
    h = __bfloat16_as_ushort(bh);
    l = __bfloat16_as_ushort(bl);
}

__device__ __forceinline__ void mma16816(float* c, const uint32_t* a, const uint32_t* b) {
    asm volatile(
        "mma.sync.aligned.m16n8k16.row.col.f32.bf16.bf16.f32 "
        "{%0,%1,%2,%3}, {%4,%5,%6,%7}, {%8,%9}, {%0,%1,%2,%3};"
        : "+f"(c[0]), "+f"(c[1]), "+f"(c[2]), "+f"(c[3])
        : "r"(a[0]), "r"(a[1]), "r"(a[2]), "r"(a[3]), "r"(b[0]), "r"(b[1]));
}

__device__ __forceinline__ uint32_t cvta_s(const void* p) {
    uint32_t a;
    asm("{ .reg .u64 t; cvta.to.shared.u64 t, %1; cvt.u32.u64 %0, t; }"
        : "=r"(a) : "l"(p));
    return a;
}

__device__ __forceinline__ void ldsm_x4(uint32_t* d, uint32_t addr) {
    asm volatile("ldmatrix.sync.aligned.m8n8.x4.shared.b16 {%0,%1,%2,%3}, [%4];"
                 : "=r"(d[0]), "=r"(d[1]), "=r"(d[2]), "=r"(d[3]) : "r"(addr));
}
__device__ __forceinline__ void ldsm_x2(uint32_t* d, uint32_t addr) {
    asm volatile("ldmatrix.sync.aligned.m8n8.x2.shared.b16 {%0,%1}, [%2];"
                 : "=r"(d[0]), "=r"(d[1]) : "r"(addr));
}

// lane offsets for ldmatrix address generation (units: elements)
// A-frag x4: lanes 0-7 rows r0..r0+7 col k0 | 8-15 rows +8 | 16-23 col +8 | 24-31 both
#define AROW(lane) (((lane) & 7) + (((lane) >> 3) & 1) * 8)
#define ACOL(lane) (((lane) >> 4) * 8)
// B-frag x2: lanes 0-7 rows n0..n0+7 col k0 | 8-15 rows n0..n0+7 col k0+8
#define BROW(lane) ((lane) & 7)
#define BCOL(lane) ((((lane) >> 3) & 1) * 8)

#define STRP 24  // padded row stride (ushorts) for 16-wide tiles: 12r mod 32 all-distinct

// ============================================================================
// Projection: Out[b,h,l,e] = sum_d A[b*LQ+l, d] * W[h,d,e]
// GEMM M=8192, N=1024, K=1024. Block 128x128, 8 warps (4m x 2n), k-step 16,
// split-bf16 (3 MMA products), 2-stage double buffer, ldmatrix frag loads.
// ============================================================================
__global__ void __launch_bounds__(256) proj_tc(const float* __restrict__ A,
                                               const float* __restrict__ W,
                                               float* __restrict__ Out)
{
    __shared__ unsigned short Ah[2][128][STRP], Al[2][128][STRP];
    __shared__ unsigned short Bh[2][128][STRP], Bl[2][128][STRP];

    const int tid = threadIdx.x;
    const int wid = tid >> 5;
    const int lane = tid & 31;
    const int gid = lane >> 2;
    const int tig = lane & 3;
    const int wm = wid & 3;
    const int wn = wid >> 2;
    const int row0 = blockIdx.y * 128;
    const int col0 = blockIdx.x * 128;

    const uint32_t ah_u = cvta_s(Ah), al_u = cvta_s(Al);
    const uint32_t bh_u = cvta_s(Bh), bl_u = cvta_s(Bl);
    const uint32_t aoff = ((wm * 32 + AROW(lane)) * STRP + ACOL(lane)) * 2;
    const uint32_t boff = ((wn * 64 + BROW(lane)) * STRP + BCOL(lane)) * 2;
    const uint32_t BUFB = 128 * STRP * 2;  // bytes per stage

    const int ar0 = tid >> 2;
    const int ac0 = (tid & 3) << 2;
    const int bn = tid & 127;
    const int bkg = (tid >> 7) << 3;
    const int ng = col0 + bn;
    const int bh_ = ng >> 6, be = ng & 63;
    const float* wbase = &W[(size_t)(bh_ << 10) * 64 + be];

    float acc[2][8][4];
#pragma unroll
    for (int i = 0; i < 2; i++)
#pragma unroll
        for (int j = 0; j < 8; j++)
#pragma unroll
            for (int t = 0; t < 4; t++) acc[i][j][t] = 0.f;

    float4 va[2];
    float vb[8];

#pragma unroll
    for (int i = 0; i < 2; i++)
        va[i] = *(const float4*)&A[(size_t)(row0 + ar0 + i * 64) * DM_ + ac0];
#pragma unroll
    for (int j = 0; j < 8; j++) vb[j] = wbase[(size_t)(bkg + j) * 64];
#pragma unroll
    for (int i = 0; i < 2; i++) {
        ushort4 h, l;
        split2(va[i].x, h.x, l.x); split2(va[i].y, h.y, l.y);
        split2(va[i].z, h.z, l.z); split2(va[i].w, h.w, l.w);
        *(ushort4*)&Ah[0][ar0 + i * 64][ac0] = h;
        *(ushort4*)&Al[0][ar0 + i * 64][ac0] = l;
    }
#pragma unroll
    for (int j = 0; j < 8; j++) split2(vb[j], Bh[0][bn][bkg + j], Bl[0][bn][bkg + j]);
    __syncthreads();

    const int NSTEP = DM_ / 16;  // 64
    for (int s = 0; s < NSTEP; s++) {
        const int buf = s & 1;
        const int k1 = (s + 1) * 16;
        if (s + 1 < NSTEP) {
#pragma unroll
            for (int i = 0; i < 2; i++)
                va[i] = *(const float4*)&A[(size_t)(row0 + ar0 + i * 64) * DM_ + k1 + ac0];
#pragma unroll
            for (int j = 0; j < 8; j++) vb[j] = wbase[(size_t)(k1 + bkg + j) * 64];
        }

        const uint32_t ab = buf * BUFB;
        uint32_t ah[2][4], al[2][4];
#pragma unroll
        for (int mi = 0; mi < 2; mi++) {
            ldsm_x4(ah[mi], ah_u + ab + aoff + mi * (16 * STRP * 2));
            ldsm_x4(al[mi], al_u + ab + aoff + mi * (16 * STRP * 2));
        }
        uint32_t bhf[8][2], blf[8][2];
#pragma unroll
        for (int ni = 0; ni < 8; ni++) {
            ldsm_x2(bhf[ni], bh_u + ab + boff + ni * (8 * STRP * 2));
            ldsm_x2(blf[ni], bl_u + ab + boff + ni * (8 * STRP * 2));
        }
#pragma unroll
        for (int ni = 0; ni < 8; ni++)
#pragma unroll
            for (int mi = 0; mi < 2; mi++) {
                mma16816(acc[mi][ni], ah[mi], bhf[ni]);
                mma16816(acc[mi][ni], ah[mi], blf[ni]);
                mma16816(acc[mi][ni], al[mi], bhf[ni]);
            }

        if (s + 1 < NSTEP) {
            const int nb = buf ^ 1;
#pragma unroll
            for (int i = 0; i < 2; i++) {
                ushort4 h, l;
                split2(va[i].x, h.x, l.x); split2(va[i].y, h.y, l.y);
                split2(va[i].z, h.z, l.z); split2(va[i].w, h.w, l.w);
                *(ushort4*)&Ah[nb][ar0 + i * 64][ac0] = h;
                *(ushort4*)&Al[nb][ar0 + i * 64][ac0] = l;
            }
#pragma unroll
            for (int j = 0; j < 8; j++)
                split2(vb[j], Bh[nb][bn][bkg + j], Bl[nb][bn][bkg + j]);
        }
        __syncthreads();
    }

    // Epilogue: write fp32 to (B,H,L,64)
#pragma unroll
    for (int mi = 0; mi < 2; mi++) {
#pragma unroll
        for (int ni = 0; ni < 8; ni++) {
            int n = col0 + wn * 64 + ni * 8 + 2 * tig;
            int hh = n >> 6, e = n & 63;
            int row = row0 + wm * 32 + mi * 16 + gid;
            int b = row >> 11, l = row & 2047;
            size_t base = (size_t)((b << 4) + hh) * 2048 + l;
            *(float2*)&Out[base * 64 + e] = make_float2(acc[mi][ni][0], acc[mi][ni][1]);
            row += 8;
            b = row >> 11; l = row & 2047;
            base = (size_t)((b << 4) + hh) * 2048 + l;
            *(float2*)&Out[base * 64 + e] = make_float2(acc[mi][ni][2], acc[mi][ni][3]);
        }
    }
}

// ============================================================================
// Scores: whole-K-in-smem, CTA = 128 q x 256 k for one bh. ldmatrix frags,
// batched MMAs, shfl-widened float4 stores.
// ============================================================================
#define SC_STR 72
#define SC_SMEM_BYTES ((2 * 128 * SC_STR + 2 * 256 * SC_STR) * 2)  // 110592

__global__ void __launch_bounds__(256) scores_tc(const float* __restrict__ Q,
                                                 const float* __restrict__ K,
                                                 float* __restrict__ S)
{
    extern __shared__ unsigned short sm[];
    unsigned short* Qh = sm;
    unsigned short* Ql = sm + 128 * SC_STR;
    unsigned short* Kh = sm + 2 * 128 * SC_STR;
    unsigned short* Kl = sm + 2 * 128 * SC_STR + 256 * SC_STR;

    const int tid = threadIdx.x;
    const int wid = tid >> 5;
    const int lane = tid & 31;
    const int gid = lane >> 2;
    const int tig = lane & 3;
    const int wm = wid & 3;
    const int wn = wid >> 2;
    const int bh = blockIdx.z;
    const int row0 = blockIdx.y * 128;
    const int col0 = blockIdx.x * 256;
    const float* Qb = Q + (size_t)bh * LQ_ * DK_;
    const float* Kb = K + (size_t)bh * LK_ * DK_;

#pragma unroll
    for (int i = 0; i < 8; i++) {
        int idx = tid + i * 256;
        int r = idx >> 4;
        int c4 = (idx & 15) << 2;
        float4 v = *(const float4*)&Qb[(size_t)(row0 + r) * 64 + c4];
        ushort4 h, l;
        split2(v.x, h.x, l.x); split2(v.y, h.y, l.y);
        split2(v.z, h.z, l.z); split2(v.w, h.w, l.w);
        *(ushort4*)&Qh[r * SC_STR + c4] = h;
        *(ushort4*)&Ql[r * SC_STR + c4] = l;
    }
#pragma unroll
    for (int i = 0; i < 16; i++) {
        int idx = tid + i * 256;
        int r = idx >> 4;
        int c4 = (idx & 15) << 2;
        float4 v = *(const float4*)&Kb[(size_t)(col0 + r) * 64 + c4];
        ushort4 h, l;
        split2(v.x, h.x, l.x); split2(v.y, h.y, l.y);
        split2(v.z, h.z, l.z); split2(v.w, h.w, l.w);
        *(ushort4*)&Kh[r * SC_STR + c4] = h;
        *(ushort4*)&Kl[r * SC_STR + c4] = l;
    }
    __syncthreads();

    const uint32_t qh_u = cvta_s(Qh), ql_u = cvta_s(Ql);
    const uint32_t kh_u = cvta_s(Kh), kl_u = cvta_s(Kl);
    const uint32_t aoff = ((wm * 32 + AROW(lane)) * SC_STR + ACOL(lane)) * 2;
    const uint32_t boff = ((wn * 64 + BROW(lane)) * SC_STR + BCOL(lane)) * 2;

    const float scale = 0.125f;
    float* Sb = S + (size_t)bh * LQ_ * LK_;

#pragma unroll
    for (int ct = 0; ct < 2; ct++) {
        float acc[2][8][4];
#pragma unroll
        for (int i = 0; i < 2; i++)
#pragma unroll
            for (int j = 0; j < 8; j++)
#pragma unroll
                for (int t = 0; t < 4; t++) acc[i][j][t] = 0.f;

        const uint32_t ctoff = ct * (128 * SC_STR * 2);
#pragma unroll
        for (int ks = 0; ks < 4; ks++) {
            const uint32_t kb = ks * 32;  // 16 elems * 2B
            uint32_t ah[2][4], al[2][4];
#pragma unroll
            for (int mi = 0; mi < 2; mi++) {
                ldsm_x4(ah[mi], qh_u + aoff + mi * (16 * SC_STR * 2) + kb);
                ldsm_x4(al[mi], ql_u + aoff + mi * (16 * SC_STR * 2) + kb);
            }
            uint32_t bhf[8][2], blf[8][2];
#pragma unroll
            for (int ni = 0; ni < 8; ni++) {
                ldsm_x2(bhf[ni], kh_u + ctoff + boff + ni * (8 * SC_STR * 2) + kb);
                ldsm_x2(blf[ni], kl_u + ctoff + boff + ni * (8 * SC_STR * 2) + kb);
            }
#pragma unroll
            for (int ni = 0; ni < 8; ni++)
#pragma unroll
                for (int mi = 0; mi < 2; mi++) {
                    mma16816(acc[mi][ni], ah[mi], bhf[ni]);
                    mma16816(acc[mi][ni], ah[mi], blf[ni]);
                    mma16816(acc[mi][ni], al[mi], bhf[ni]);
                }
        }

        // shfl-widened float4 epilogue
#pragma unroll
        for (int mi = 0; mi < 2; mi++) {
#pragma unroll
            for (int ni = 0; ni < 8; ni++) {
                float c0 = acc[mi][ni][0] * scale, c1 = acc[mi][ni][1] * scale;
                float c2 = acc[mi][ni][2] * scale, c3 = acc[mi][ni][3] * scale;
                float p0 = __shfl_xor_sync(0xffffffffu, c0, 1);
                float p1 = __shfl_xor_sync(0xffffffffu, c1, 1);
                float p2 = __shfl_xor_sync(0xffffffffu, c2, 1);
                float p3 = __shfl_xor_sync(0xffffffffu, c3, 1);
                int row = row0 + wm * 32 + mi * 16 + gid;
                int colb = col0 + ct * 128 + wn * 64 + ni * 8 + (tig >> 1) * 4;
                if ((lane & 1) == 0) {
                    *(float4*)&Sb[(size_t)row * LK_ + colb] = make_float4(c0, c1, p0, p1);
                } else {
                    *(float4*)&Sb[(size_t)(row + 8) * LK_ + colb] = make_float4(p2, p3, c2, c3);
                }
            }
        }
    }
}

// ============================================================================
// Row softmax in place
// ============================================================================
__global__ void __launch_bounds__(256) softmax_kernel(float* __restrict__ A)
{
    const size_t row = blockIdx.x;
    float* p = A + row * (size_t)LK_;
    const int tid = threadIdx.x;
    const int lane = tid & 31, wid = tid >> 5;

    float4 v0 = *(const float4*)&p[tid * 8];
    float4 v1 = *(const float4*)&p[tid * 8 + 4];

    float m = fmaxf(fmaxf(fmaxf(v0.x, v0.y), fmaxf(v0.z, v0.w)),
                    fmaxf(fmaxf(v1.x, v1.y), fmaxf(v1.z, v1.w)));
#pragma unroll
    for (int o = 16; o; o >>= 1) m = fmaxf(m, __shfl_xor_sync(0xffffffffu, m, o));

    __shared__ float red[8];
    if (lane == 0) red[wid] = m;
    __syncthreads();
    float bm = red[0];
#pragma unroll
    for (int i = 1; i < 8; i++) bm = fmaxf(bm, red[i]);

    v0.x = __expf(v0.x - bm); v0.y = __expf(v0.y - bm);
    v0.z = __expf(v0.z - bm); v0.w = __expf(v0.w - bm);
    v1.x = __expf(v1.x - bm); v1.y = __expf(v1.y - bm);
    v1.z = __expf(v1.z - bm); v1.w = __expf(v1.w - bm);

    float s = (v0.x + v0.y) + (v0.z + v0.w) + (v1.x + v1.y) + (v1.z + v1.w);
#pragma unroll
    for (int o = 16; o; o >>= 1) s += __shfl_xor_sync(0xffffffffu, s, o);

    __syncthreads();
    if (lane == 0) red[wid] = s;
    __syncthreads();
    float bs = 0.f;
#pragma unroll
    for (int i = 0; i < 8; i++) bs += red[i];
    float inv = 1.0f / bs;

    v0.x *= inv; v0.y *= inv; v0.z *= inv; v0.w *= inv;
    v1.x *= inv; v1.y *= inv; v1.z *= inv; v1.w *= inv;
    *(float4*)&p[tid * 8] = v0;
    *(float4*)&p[tid * 8 + 4] = v1;
}

// ============================================================================
// Context: ctx[b,q,h*64+e] = sum_k P[bh,q,k] * V[bh,k,e]
// Block 128x64, k-step 16 (128 steps), double-buffered, ldmatrix frags.
// ============================================================================
__global__ void __launch_bounds__(256) ctx_tc(const float* __restrict__ P,
                                              const float* __restrict__ V)
{
    __shared__ unsigned short Ah[2][128][STRP], Al[2][128][STRP];
    __shared__ unsigned short Bh[2][64][STRP], Bl[2][64][STRP];

    const int tid = threadIdx.x;
    const int wid = tid >> 5;
    const int lane = tid & 31;
    const int gid = lane >> 2;
    const int tig = lane & 3;
    const int bh = blockIdx.z;
    const int row0 = blockIdx.y * 128;
    const float* Pb = P + (size_t)bh * LQ_ * LK_;
    const float* Vb = V + (size_t)bh * LK_ * DV_;

    const uint32_t ah_u = cvta_s(Ah), al_u = cvta_s(Al);
    const uint32_t bh_u = cvta_s(Bh), bl_u = cvta_s(Bl);
    const uint32_t aoff = ((wid * 16 + AROW(lane)) * STRP + ACOL(lane)) * 2;
    const uint32_t boff = (BROW(lane) * STRP + BCOL(lane)) * 2;
    const uint32_t ABUF = 128 * STRP * 2;
    const uint32_t BBUF = 64 * STRP * 2;

    const int ar0 = tid >> 2;
    const int ac0 = (tid & 3) << 2;
    const int bn = tid & 63;
    const int bkg = (tid >> 6) << 2;

    float acc[8][4];
#pragma unroll
    for (int j = 0; j < 8; j++)
#pragma unroll
        for (int t = 0; t < 4; t++) acc[j][t] = 0.f;

    float4 va[2];
    float vb[4];

#pragma unroll
    for (int i = 0; i < 2; i++)
        va[i] = *(const float4*)&Pb[(size_t)(row0 + ar0 + i * 64) * LK_ + ac0];
#pragma unroll
    for (int j = 0; j < 4; j++) vb[j] = Vb[(size_t)(bkg + j) * 64 + bn];
#pragma unroll
    for (int i = 0; i < 2; i++) {
        ushort4 h, l;
        split2(va[i].x, h.x, l.x); split2(va[i].y, h.y, l.y);
        split2(va[i].z, h.z, l.z); split2(va[i].w, h.w, l.w);
        *(ushort4*)&Ah[0][ar0 + i * 64][ac0] = h;
        *(ushort4*)&Al[0][ar0 + i * 64][ac0] = l;
    }
#pragma unroll
    for (int j = 0; j < 4; j++) split2(vb[j], Bh[0][bn][bkg + j], Bl[0][bn][bkg + j]);
    __syncthreads();

    const int NSTEP = LK_ / 16;  // 128
    for (int s = 0; s < NSTEP; s++) {
        const int buf = s & 1;
        const int k1 = (s + 1) * 16;
        if (s + 1 < NSTEP) {
#pragma unroll
            for (int i = 0; i < 2; i++)
                va[i] = *(const float4*)&Pb[(size_t)(row0 + ar0 + i * 64) * LK_ + k1 + ac0];
#pragma unroll
            for (int j = 0; j < 4; j++) vb[j] = Vb[(size_t)(k1 + bkg + j) * 64 + bn];
        }

        uint32_t ah[4], al[4];
        ldsm_x4(ah, ah_u + buf * ABUF + aoff);
        ldsm_x4(al, al_u + buf * ABUF + aoff);
        uint32_t bhf[8][2], blf[8][2];
#pragma unroll
        for (int ni = 0; ni < 8; ni++) {
            ldsm_x2(bhf[ni], bh_u + buf * BBUF + boff + ni * (8 * STRP * 2));
            ldsm_x2(blf[ni], bl_u + buf * BBUF + boff + ni * (8 * STRP * 2));
        }
#pragma unroll
        for (int ni = 0; ni < 8; ni++) {
            mma16816(acc[ni], ah, bhf[ni]);
            mma16816(acc[ni], ah, blf[ni]);
            mma16816(acc[ni], al, bhf[ni]);
        }

        if (s + 1 < NSTEP) {
            const int nb = buf ^ 1;
#pragma unroll
            for (int i = 0; i < 2; i++) {
                ushort4 h, l;
                split2(va[i].x, h.x, l.x); split2(va[i].y, h.y, l.y);
                split2(va[i].z, h.z, l.z); split2(va[i].w, h.w, l.w);
                *(ushort4*)&Ah[nb][ar0 + i * 64][ac0] = h;
                *(ushort4*)&Al[nb][ar0 + i * 64][ac0] = l;
            }
#pragma unroll
            for (int j = 0; j < 4; j++)
                split2(vb[j], Bh[nb][bn][bkg + j], Bl[nb][bn][bkg + j]);
        }
        __syncthreads();
    }

    const int b = bh >> 4, hh = bh & 15;
#pragma unroll
    for (int ni = 0; ni < 8; ni++) {
        int row = row0 + wid * 16 + gid;
        int col = hh * 64 + ni * 8 + 2 * tig;
        *(float2*)&g_ctx[(size_t)(b * 2048 + row) * 1024 + col] =
            make_float2(acc[ni][0], acc[ni][1]);
        *(float2*)&g_ctx[(size_t)(b * 2048 + row + 8) * 1024 + col] =
            make_float2(acc[ni][2], acc[ni][3]);
    }
}

// ============================================================================
// Output projection: out = ctx @ wo; M=8192, N=K=1024. Same scheme as proj.
// ============================================================================
__global__ void __launch_bounds__(256) outproj_tc(const float* __restrict__ W,
                                                  float* __restrict__ C)
{
    __shared__ unsigned short Ah[2][128][STRP], Al[2][128][STRP];
    __shared__ unsigned short Bh[2][128][STRP], Bl[2][128][STRP];

    const int tid = threadIdx.x;
    const int wid = tid >> 5;
    const int lane = tid & 31;
    const int gid = lane >> 2;
    const int tig = lane & 3;
    const int wm = wid & 3;
    const int wn = wid >> 2;
    const int row0 = blockIdx.y * 128;
    const int col0 = blockIdx.x * 128;

    const uint32_t ah_u = cvta_s(Ah), al_u = cvta_s(Al);
    const uint32_t bh_u = cvta_s(Bh), bl_u = cvta_s(Bl);
    const uint32_t aoff = ((wm * 32 + AROW(lane)) * STRP + ACOL(lane)) * 2;
    const uint32_t boff = ((wn * 64 + BROW(lane)) * STRP + BCOL(lane)) * 2;
    const uint32_t BUFB = 128 * STRP * 2;

    const int ar0 = tid >> 2;
    const int ac0 = (tid & 3) << 2;
    const int bn = tid & 127;
    const int bkg = (tid >> 7) << 3;

    float acc[2][8][4];
#pragma unroll
    for (int i = 0; i < 2; i++)
#pragma unroll
        for (int j = 0; j < 8; j++)
#pragma unroll
            for (int t = 0; t < 4; t++) acc[i][j][t] = 0.f;

    float4 va[2];
    float vb[8];

#pragma unroll
    for (int i = 0; i < 2; i++)
        va[i] = *(const float4*)&g_ctx[(size_t)(row0 + ar0 + i * 64) * DM_ + ac0];
#pragma unroll
    for (int j = 0; j < 8; j++) vb[j] = W[(size_t)(bkg + j) * DM_ + col0 + bn];
#pragma unroll
    for (int i = 0; i < 2; i++) {
        ushort4 h, l;
        split2(va[i].x, h.x, l.x); split2(va[i].y, h.y, l.y);
        split2(va[i].z, h.z, l.z); split2(va[i].w, h.w, l.w);
        *(ushort4*)&Ah[0][ar0 + i * 64][ac0] = h;
        *(ushort4*)&Al[0][ar0 + i * 64][ac0] = l;
    }
#pragma unroll
    for (int j = 0; j < 8; j++) split2(vb[j], Bh[0][bn][bkg + j], Bl[0][bn][bkg + j]);
    __syncthreads();

    const int NSTEP = DM_ / 16;
    for (int s = 0; s < NSTEP; s++) {
        const int buf = s & 1;
        const int k1 = (s + 1) * 16;
        if (s + 1 < NSTEP) {
#pragma unroll
            for (int i = 0; i < 2; i++)
                va[i] = *(const float4*)&g_ctx[(size_t)(row0 + ar0 + i * 64) * DM_ + k1 + ac0];
#pragma unroll
            for (int j = 0; j < 8; j++) vb[j] = W[(size_t)(k1 + bkg + j) * DM_ + col0 + bn];
        }

        const uint32_t ab = buf * BUFB;
        uint32_t ah[2][4], al[2][4];
#pragma unroll
        for (int mi = 0; mi < 2; mi++) {
            ldsm_x4(ah[mi], ah_u + ab + aoff + mi * (16 * STRP * 2));
            ldsm_x4(al[mi], al_u + ab + aoff + mi * (16 * STRP * 2));
        }
        uint32_t bhf[8][2], blf[8][2];
#pragma unroll
        for (int ni = 0; ni < 8; ni++) {
            ldsm_x2(bhf[ni], bh_u + ab + boff + ni * (8 * STRP * 2));
            ldsm_x2(blf[ni], bl_u + ab + boff + ni * (8 * STRP * 2));
        }
#pragma unroll
        for (int ni = 0; ni < 8; ni++)
#pragma unroll
            for (int mi = 0; mi < 2; mi++) {
                mma16816(acc[mi][ni], ah[mi], bhf[ni]);
                mma16816(acc[mi][ni], ah[mi], blf[ni]);
                mma16816(acc[mi][ni], al[mi], bhf[ni]);
            }

        if (s + 1 < NSTEP) {
            const int nb = buf ^ 1;
#pragma unroll
            for (int i = 0; i < 2; i++) {
                ushort4 h, l;
                split2(va[i].x, h.x, l.x); split2(va[i].y, h.y, l.y);
                split2(va[i].z, h.z, l.z); split2(va[i].w, h.w, l.w);
                *(ushort4*)&Ah[nb][ar0 + i * 64][ac0] = h;
                *(ushort4*)&Al[nb][ar0 + i * 64][ac0] = l;
            }
#pragma unroll
            for (int j = 0; j < 8; j++)
                split2(vb[j], Bh[nb][bn][bkg + j], Bl[nb][bn][bkg + j]);
        }
        __syncthreads();
    }

#pragma unroll
    for (int mi = 0; mi < 2; mi++) {
#pragma unroll
        for (int ni = 0; ni < 8; ni++) {
            int row = row0 + wm * 32 + mi * 16 + gid;
            int col = col0 + wn * 64 + ni * 8 + 2 * tig;
            *(float2*)&C[(size_t)row * DM_ + col] =
                make_float2(acc[mi][ni][0], acc[mi][ni][1]);
            *(float2*)&C[(size_t)(row + 8) * DM_ + col] =
                make_float2(acc[mi][ni][2], acc[mi][ni][3]);
        }
    }
}

// ============================================================================
// Launch
// ============================================================================
extern "C" void kernel_launch(void* const* d_in, const int* in_sizes, int n_in,
                              void* d_out, int out_size)
{
    const float* q  = (const float*)d_in[0];
    const float* k  = (const float*)d_in[1];
    const float* v  = (const float*)d_in[2];
    const float* wq = (const float*)d_in[3];
    const float* wk = (const float*)d_in[4];
    const float* wv = (const float*)d_in[5];
    const float* wo = (const float*)d_in[6];
    float* out = (float*)d_out;

    const long long OUT_E = (long long)B_ * LQ_ * DM_;        // 8,388,608
    const long long ATT_E = (long long)B_ * H_ * LQ_ * LK_;   // 268,435,456

    float* attn;
    if ((long long)out_size >= OUT_E + ATT_E) {
        attn = out + OUT_E;                 // tuple output: [out, attn]
    } else {
        void* p = nullptr;
        cudaGetSymbolAddress(&p, g_attn_fb);
        attn = (float*)p;
    }

    float *gq, *gk, *gv;
    cudaGetSymbolAddress((void**)&gq, g_Q);
    cudaGetSymbolAddress((void**)&gk, g_K);
    cudaGetSymbolAddress((void**)&gv, g_V);

    cudaFuncSetAttribute(scores_tc,
                         cudaFuncAttributeMaxDynamicSharedMemorySize, SC_SMEM_BYTES);

    dim3 t(256);
    proj_tc<<<dim3(8, 64), t>>>(q, wq, gq);
    proj_tc<<<dim3(8, 64), t>>>(k, wk, gk);
    proj_tc<<<dim3(8, 64), t>>>(v, wv, gv);
    scores_tc<<<dim3(8, 16, 64), t, SC_SMEM_BYTES>>>(gq, gk, attn);
    softmax_kernel<<<dim3(B_ * H_ * LQ_), t>>>(attn);
    ctx_tc<<<dim3(1, 16, 64), t>>>(attn, gv);
    outproj_tc<<<dim3(8, 64), t>>>(wo, out);
}